// round 12
// baseline (speedup 1.0000x reference)
#include <cuda_runtime.h>
#include <cuda_bf16.h>

#define B_    32
#define C_    768
#define CR_   192
#define BC_   (B_ * C_)     // 24576
#define BCR_  (B_ * CR_)    // 6144
#define PCTA  3072          // pool CTAs
#define MCTA  768           // CTAs that also run the mlp tail (6144 dots / 8 warps)

// Scratch (device globals — no allocation allowed in kernel_launch)
__device__ float    d_s[BC_];    // pooled means [B, C]
__device__ float    d_h[BCR_];   // hidden (swish) [B, Cr]
__device__ unsigned done_cnt;    // pool completion tickets (reset each launch)
__device__ unsigned fin_cnt;     // mlp completion tickets (reset each launch)

// 32-byte L2-persist load (sm_103a: evict_last requires .v8.b32 width).
struct F8 { float a0,a1,a2,a3,a4,a5,a6,a7; };
__device__ __forceinline__ F8 ld_evict_last_32B(const void* p) {
    F8 v;
    asm volatile(
        "ld.global.L2::evict_last.v8.b32 {%0,%1,%2,%3,%4,%5,%6,%7}, [%8];"
        : "=f"(v.a0), "=f"(v.a1), "=f"(v.a2), "=f"(v.a3),
          "=f"(v.a4), "=f"(v.a5), "=f"(v.a6), "=f"(v.a7)
        : "l"(p));
    return v;
}

// ---------------------------------------------------------------------------
// Kernel 1: pool + fused MLP tail.
// Pool: one warp per (b,c) channel, evict_last 32B loads (x persists in L2).
// Tail: each CTA takes a ticket when done; the last MCTA ticket-holders wait
// for all pools, then compute 8 h-dots each (w1 reads overlap pool stragglers).
// Counters self-reset (last mlp finisher) -> safe across graph replays.
// ---------------------------------------------------------------------------
__global__ __launch_bounds__(256) void pool_mlp_kernel(const float* __restrict__ x,
                                                       const float* __restrict__ w1,
                                                       const float* __restrict__ b1) {
    int tid  = threadIdx.x;
    int warp = tid >> 5;
    int lane = tid & 31;
    int ch   = blockIdx.x * 8 + warp;

    const char* base = reinterpret_cast<const char*>(x) + (size_t)ch * 4096;
    float sum = 0.0f;
#pragma unroll
    for (int i = 0; i < 4; i++) {
        F8 v = ld_evict_last_32B(base + (lane + i * 32) * 32);
        sum += ((v.a0 + v.a1) + (v.a2 + v.a3)) + ((v.a4 + v.a5) + (v.a6 + v.a7));
    }
#pragma unroll
    for (int o = 16; o; o >>= 1) sum += __shfl_xor_sync(0xffffffffu, sum, o);
    if (lane == 0) d_s[ch] = sum * (1.0f / 1024.0f);

    // ---- ticket + tail-select -------------------------------------------
    __shared__ unsigned ticket_sm;
    __syncthreads();
    if (tid == 0) {
        __threadfence();                       // d_s visible before ticket
        ticket_sm = atomicAdd(&done_cnt, 1);
    }
    __syncthreads();
    unsigned ticket = ticket_sm;
    if (ticket < PCTA - MCTA) return;          // early finishers exit

    // ---- wait for all pools, then 8 dots per CTA (1 per warp) ------------
    if (tid == 0) {
        while (*(volatile unsigned*)&done_cnt < PCTA) __nanosleep(64);
    }
    __syncthreads();
    __threadfence();

    unsigned slice = ticket - (PCTA - MCTA);   // 0..767
    int gw = slice * 8 + warp;                 // dot index 0..6143
    int j  = gw % CR_;
    int b  = gw / CR_;
    const float* wr = w1 + (size_t)j * C_;
    const float* sr = d_s + b * C_;
    float acc = 0.0f;
#pragma unroll
    for (int t = 0; t < C_ / 32; t++) {        // 24 independent loads
        int k = lane + t * 32;
        acc += sr[k] * wr[k];
    }
#pragma unroll
    for (int o = 16; o; o >>= 1) acc += __shfl_xor_sync(0xffffffffu, acc, o);
    if (lane == 0) {
        float h = acc + b1[j];
        d_h[b * CR_ + j] = h / (1.0f + __expf(-h));
    }

    // ---- reset counters for the next graph replay ------------------------
    __syncthreads();
    if (tid == 0) {
        __threadfence();
        if (atomicAdd(&fin_cnt, 1) == MCTA - 1) {
            fin_cnt  = 0;
            done_cnt = 0;
            __threadfence();
        }
    }
}

// ---------------------------------------------------------------------------
// Kernel 2: fused gate + scale. One CTA per (b,c) channel, REVERSED order so
// it consumes the MRU tail of pool's L2 stream first. Warp 0 computes
// g = sigmoid(<h[b,:], w2[c,:]> + b2[c]) concurrently with the x loads.
// Reads: evict-first (last use). Stores: evict-first (best measured).
// ---------------------------------------------------------------------------
__global__ __launch_bounds__(256) void scale_kernel(const float* __restrict__ x,
                                                    const float* __restrict__ w2,
                                                    const float* __restrict__ b2,
                                                    float* __restrict__ out) {
    __shared__ float g_sm;
    int ch  = (BC_ - 1) - blockIdx.x;
    int tid = threadIdx.x;

    const float4* xp = reinterpret_cast<const float4*>(x) + (size_t)ch * 256 + tid;
    float4 v = __ldcs(xp);

    if (tid < 32) {
        int c = ch % C_;
        int b = ch / C_;
        const float* wr = w2 + (size_t)c * CR_;
        const float* hr = d_h + b * CR_;
        float acc = 0.0f;
#pragma unroll
        for (int t = 0; t < CR_ / 32; t++) {
            int k = tid + t * 32;
            acc += hr[k] * wr[k];
        }
#pragma unroll
        for (int o = 16; o; o >>= 1) acc += __shfl_xor_sync(0xffffffffu, acc, o);
        if (tid == 0)
            g_sm = 1.0f / (1.0f + __expf(-(acc + b2[c])));
    }
    __syncthreads();

    float g = g_sm;
    v.x *= g; v.y *= g; v.z *= g; v.w *= g;
    __stcs(reinterpret_cast<float4*>(out) + (size_t)ch * 256 + tid, v);
}

// ---------------------------------------------------------------------------
extern "C" void kernel_launch(void* const* d_in, const int* in_sizes, int n_in,
                              void* d_out, int out_size) {
    const float* x  = (const float*)d_in[0];
    const float* w1 = (const float*)d_in[1];
    const float* b1 = (const float*)d_in[2];
    const float* w2 = (const float*)d_in[3];
    const float* b2 = (const float*)d_in[4];
    float* out = (float*)d_out;

    pool_mlp_kernel<<<PCTA, 256>>>(x, w1, b1);   // 3072 CTAs, mlp fused in tail
    scale_kernel<<<BC_, 256>>>(x, w2, b2, out);  // 24576 CTAs, CTA/channel
}